// round 11
// baseline (speedup 1.0000x reference)
#include <cuda_runtime.h>
#include <cuda_bf16.h>
#include <math_constants.h>
#include <cstdint>

// Problem constants (fixed shapes per reference)
constexpr int NN = 100000;   // nodes
constexpr int EE = 1600000;  // edges
constexpr int HDc = 64;      // H*D
constexpr int FIN = 128;

// ---------------- scratch (static device globals; no runtime alloc) -------
__device__ float g_q[(size_t)NN * HDc];
__device__ float g_k[(size_t)NN * HDc];
__device__ float g_v[(size_t)NN * HDc];
__device__ float g_skip[(size_t)NN * HDc];
__device__ int   g_cnt[NN];
__device__ int   g_rowstart[NN + 1];
__device__ int   g_cursor[NN];
__device__ int   g_csrc[EE];
__device__ int   g_bsum[128];
// Pre-split bf16 weights, TRANSPOSED: [4 matrices][64 n][128 k] (k contiguous)
__device__ __nv_bfloat16 g_Wh[4 * 64 * 128];
__device__ __nv_bfloat16 g_Wl[4 * 64 * 128];

// ---------------- CSR build ------------------------------------------------
__global__ void zero_k() {
    int i = blockIdx.x * blockDim.x + threadIdx.x;
    if (i < NN) g_cnt[i] = 0;
}

// int4-vectorized histogram: 4 edges per thread
__global__ void hist_k(const int* __restrict__ dst) {
    int i = blockIdx.x * blockDim.x + threadIdx.x;
    if (i < EE / 4) {
        int4 d = ((const int4*)dst)[i];
        atomicAdd(&g_cnt[d.x], 1);
        atomicAdd(&g_cnt[d.y], 1);
        atomicAdd(&g_cnt[d.z], 1);
        atomicAdd(&g_cnt[d.w], 1);
    }
}

__global__ void scan_reduce_k() {
    __shared__ int sb[1024];
    int t = threadIdx.x;
    int i = blockIdx.x * 1024 + t;
    sb[t] = (i < NN) ? g_cnt[i] : 0;
    __syncthreads();
    for (int off = 512; off > 0; off >>= 1) {
        if (t < off) sb[t] += sb[t + off];
        __syncthreads();
    }
    if (t == 0) g_bsum[blockIdx.x] = sb[0];
}

__global__ void scan_mid_k(int nb) {
    __shared__ int sb[2][128];
    int t = threadIdx.x;
    int v = (t < nb) ? g_bsum[t] : 0;
    sb[0][t] = v;
    __syncthreads();
    int cur = 0;
    for (int off = 1; off < 128; off <<= 1) {
        int nv = sb[cur][t] + ((t >= off) ? sb[cur][t - off] : 0);
        sb[cur ^ 1][t] = nv;
        cur ^= 1;
        __syncthreads();
    }
    if (t < nb) g_bsum[t] = sb[cur][t] - v;  // exclusive
}

__global__ void scan_final_k() {
    __shared__ int sb[2][1024];
    int t = threadIdx.x;
    int i = blockIdx.x * 1024 + t;
    int v = (i < NN) ? g_cnt[i] : 0;
    sb[0][t] = v;
    __syncthreads();
    int cur = 0;
    for (int off = 1; off < 1024; off <<= 1) {
        int nv = sb[cur][t] + ((t >= off) ? sb[cur][t - off] : 0);
        sb[cur ^ 1][t] = nv;
        cur ^= 1;
        __syncthreads();
    }
    int incl = sb[cur][t];
    int base = g_bsum[blockIdx.x];
    if (i < NN) {
        int ex = base + incl - v;
        g_rowstart[i] = ex;
        g_cursor[i]   = ex;
        if (i == NN - 1) g_rowstart[NN] = ex + v;
    }
}

// int4-vectorized scatter: 4 edges per thread
__global__ void scatter_k(const int* __restrict__ src, const int* __restrict__ dst) {
    int i = blockIdx.x * blockDim.x + threadIdx.x;
    if (i < EE / 4) {
        int4 s4 = ((const int4*)src)[i];
        int4 d4 = ((const int4*)dst)[i];
        int p;
        p = atomicAdd(&g_cursor[d4.x], 1); g_csrc[p] = s4.x;
        p = atomicAdd(&g_cursor[d4.y], 1); g_csrc[p] = s4.y;
        p = atomicAdd(&g_cursor[d4.z], 1); g_csrc[p] = s4.z;
        p = atomicAdd(&g_cursor[d4.w], 1); g_csrc[p] = s4.w;
    }
}

// ---------------- weight pre-split: fp32 [k][n] -> bf16 hi/lo W^T [n][k] ----
struct WPtrs { const float* W[4]; };

__global__ void wprep_k(WPtrs wp) {
    int e = blockIdx.x * blockDim.x + threadIdx.x;
    if (e >= 4 * 64 * 128) return;
    int m = e >> 13;
    int rest = e & 8191;
    int n = rest >> 7;     // 0..63
    int k = rest & 127;    // 0..127
    float x = wp.W[m][(size_t)k * 64 + n];
    __nv_bfloat16 hi = __float2bfloat16_rn(x);
    __nv_bfloat16 lo = __float2bfloat16_rn(x - __bfloat162float(hi));
    g_Wh[m * 8192 + n * 128 + k] = hi;
    g_Wl[m * 8192 + n * 128 + k] = lo;
}

// ---------------- mma.sync split-bf16 GEMM ---------------------------------
// D = A_hi*W_hi + A_hi*W_lo + A_lo*W_hi, fp32 accum (HMMA m16n8k16).
// Block: 256 thr = 8 warps. Warp (wm=wid>>2 in {0,1}, wn=wid&3 = matrix id).
// Warp tile: 32 rows x 64 cols of its matrix. Block: 4 M-tiles of 64 rows
// (weight staging amortized over 256 rows).
constexpr int PAD = 272;
constexpr int SW_H = 0;                       // 256 rows * 272 = 69632
constexpr int SW_L = 256 * PAD;               // 69632
constexpr int SA_H = 2 * SW_L;                // 139264 (64 rows * 272)
constexpr int SA_L = SA_H + 64 * PAD;         // 156672
constexpr int SM_TOT = SA_L + 64 * PAD;       // 174080

struct BiasPtrs { const float* b[4]; };

__device__ __forceinline__ void mma16816(float c[4], const uint32_t a[4],
                                         uint32_t b0, uint32_t b1) {
    asm volatile(
        "mma.sync.aligned.m16n8k16.row.col.f32.bf16.bf16.f32 "
        "{%0,%1,%2,%3}, {%4,%5,%6,%7}, {%8,%9}, {%0,%1,%2,%3};"
        : "+f"(c[0]), "+f"(c[1]), "+f"(c[2]), "+f"(c[3])
        : "r"(a[0]), "r"(a[1]), "r"(a[2]), "r"(a[3]), "r"(b0), "r"(b1));
}

__global__ void __launch_bounds__(256) gemm_mma_k(const float* __restrict__ feat,
                                                  BiasPtrs bp) {
    extern __shared__ char smem[];
    const int tid = threadIdx.x;
    const int wid = tid >> 5;
    const int lane = tid & 31;
    const int gid = lane >> 2;   // 0..7 (row within 8-block)
    const int tig = lane & 3;    // 0..3
    const int wm = wid >> 2;     // 0..1 : M half
    const int wn = wid & 3;      // 0..3 : matrix id

    // ---- stage all weights once (hi+lo, padded rows) ----
    {
        const uint4* wh = (const uint4*)g_Wh;
        const uint4* wl = (const uint4*)g_Wl;
        for (int i = tid; i < 4096; i += 256) {
            int mn = i >> 4;          // 0..255 (matrix*64 + n)
            int chunk = i & 15;       // 16-byte chunk within 256B row
            *(uint4*)(smem + SW_H + mn * PAD + chunk * 16) = wh[i];
            *(uint4*)(smem + SW_L + mn * PAD + chunk * 16) = wl[i];
        }
    }

    float* const outs[4] = {g_q, g_k, g_v, g_skip};
    const float* bias = bp.b[wn];
    const float scale = (wn == 0) ? 0.25f : 1.0f;
    float2 bvv[8];
#pragma unroll
    for (int ni = 0; ni < 8; ni++) bvv[ni] = *(const float2*)&bias[ni * 8 + tig * 2];

    for (int t = 0; t < 4; t++) {
        const int trow0 = blockIdx.x * 256 + t * 64;
        __syncthreads();   // W ready (t=0) / previous tile's frag reads done

        // ---- stage A tile (64 rows x 128 k), split hi/lo ----
        for (int idx = tid; idx < 2048; idx += 256) {
            int r = idx >> 5;          // 0..63
            int k4 = idx & 31;         // float4 index (4 k each)
            int grow = trow0 + r;
            float4 a = (grow < NN)
                ? *(const float4*)&feat[(size_t)grow * FIN + k4 * 4]
                : make_float4(0.f, 0.f, 0.f, 0.f);
            __nv_bfloat16 h0 = __float2bfloat16_rn(a.x);
            __nv_bfloat16 h1 = __float2bfloat16_rn(a.y);
            __nv_bfloat16 h2 = __float2bfloat16_rn(a.z);
            __nv_bfloat16 h3 = __float2bfloat16_rn(a.w);
            __nv_bfloat16 l0 = __float2bfloat16_rn(a.x - __bfloat162float(h0));
            __nv_bfloat16 l1 = __float2bfloat16_rn(a.y - __bfloat162float(h1));
            __nv_bfloat16 l2 = __float2bfloat16_rn(a.z - __bfloat162float(h2));
            __nv_bfloat16 l3 = __float2bfloat16_rn(a.w - __bfloat162float(h3));
            uint2 hp, lp;
            hp.x = (uint32_t)__bfloat16_as_ushort(h0) | ((uint32_t)__bfloat16_as_ushort(h1) << 16);
            hp.y = (uint32_t)__bfloat16_as_ushort(h2) | ((uint32_t)__bfloat16_as_ushort(h3) << 16);
            lp.x = (uint32_t)__bfloat16_as_ushort(l0) | ((uint32_t)__bfloat16_as_ushort(l1) << 16);
            lp.y = (uint32_t)__bfloat16_as_ushort(l2) | ((uint32_t)__bfloat16_as_ushort(l3) << 16);
            *(uint2*)(smem + SA_H + r * PAD + k4 * 8) = hp;
            *(uint2*)(smem + SA_L + r * PAD + k4 * 8) = lp;
        }
        __syncthreads();

        // ---- main MMA loop ----
        float acc[2][8][4];
#pragma unroll
        for (int mi = 0; mi < 2; mi++)
#pragma unroll
            for (int ni = 0; ni < 8; ni++)
#pragma unroll
                for (int j = 0; j < 4; j++) acc[mi][ni][j] = 0.f;

#pragma unroll
        for (int ks = 0; ks < 8; ks++) {
            const int kcolB = (ks * 16 + tig * 2) * 2;  // byte offset of k pair
            uint32_t ah[2][4], al[2][4];
#pragma unroll
            for (int mi = 0; mi < 2; mi++) {
                const char* base = smem + (wm * 32 + mi * 16 + gid) * PAD + kcolB;
                ah[mi][0] = *(const uint32_t*)(base + SA_H);
                ah[mi][1] = *(const uint32_t*)(base + SA_H + 8 * PAD);
                ah[mi][2] = *(const uint32_t*)(base + SA_H + 16);
                ah[mi][3] = *(const uint32_t*)(base + SA_H + 8 * PAD + 16);
                al[mi][0] = *(const uint32_t*)(base + SA_L);
                al[mi][1] = *(const uint32_t*)(base + SA_L + 8 * PAD);
                al[mi][2] = *(const uint32_t*)(base + SA_L + 16);
                al[mi][3] = *(const uint32_t*)(base + SA_L + 8 * PAD + 16);
            }
            uint32_t bh[8][2], bl[8][2];
#pragma unroll
            for (int ni = 0; ni < 8; ni++) {
                const char* base = smem + (wn * 64 + ni * 8 + gid) * PAD + kcolB;
                bh[ni][0] = *(const uint32_t*)(base + SW_H);
                bh[ni][1] = *(const uint32_t*)(base + SW_H + 16);
                bl[ni][0] = *(const uint32_t*)(base + SW_L);
                bl[ni][1] = *(const uint32_t*)(base + SW_L + 16);
            }
#pragma unroll
            for (int mi = 0; mi < 2; mi++)
#pragma unroll
                for (int ni = 0; ni < 8; ni++) {
                    mma16816(acc[mi][ni], ah[mi], bh[ni][0], bh[ni][1]);
                    mma16816(acc[mi][ni], ah[mi], bl[ni][0], bl[ni][1]);
                    mma16816(acc[mi][ni], al[mi], bh[ni][0], bh[ni][1]);
                }
        }

        // ---- epilogue ----
        float* op = outs[wn];
#pragma unroll
        for (int mi = 0; mi < 2; mi++) {
            int r0 = trow0 + wm * 32 + mi * 16 + gid;
#pragma unroll
            for (int ni = 0; ni < 8; ni++) {
                int col = ni * 8 + tig * 2;
                float2 bv = bvv[ni];
                if (r0 < NN) {
                    float2 o;
                    o.x = (acc[mi][ni][0] + bv.x) * scale;
                    o.y = (acc[mi][ni][1] + bv.y) * scale;
                    *(float2*)&op[(size_t)r0 * HDc + col] = o;
                }
                if (r0 + 8 < NN) {
                    float2 o;
                    o.x = (acc[mi][ni][2] + bv.x) * scale;
                    o.y = (acc[mi][ni][3] + bv.y) * scale;
                    *(float2*)&op[(size_t)(r0 + 8) * HDc + col] = o;
                }
            }
        }
    }
}

// ---------------- fused attention + skip + LayerNorm -----------------------
// One warp per destination node; TWO edges in flight per iteration:
// lanes 0-15 process edge i, lanes 16-31 process edge i+1.
// Each sub-lane sl owns channels 4sl..4sl+3 (float4). Head h = lanes 4h..4h+3,
// dot reduced with 2 shfls (xor 1, xor 2). Online-softmax states merged
// across the two halves at the end (shfl xor 16).
__global__ void __launch_bounds__(256) attn_k(const float* __restrict__ ln_g,
                                              const float* __restrict__ ln_b,
                                              float* __restrict__ out) {
    int gw = (blockIdx.x * blockDim.x + threadIdx.x) >> 5;
    if (gw >= NN) return;
    const int lane = threadIdx.x & 31;
    const int half = lane >> 4;
    const int sl = lane & 15;
    const int c = sl * 4;

    float4 qv = *(const float4*)(g_q + (size_t)gw * HDc + c);
    int beg = g_rowstart[gw];
    int end = g_rowstart[gw + 1];

    float mm = -CUDART_INF_F, ss = 0.f;
    float4 acc = make_float4(0.f, 0.f, 0.f, 0.f);

    for (int i = beg; i < end; i += 2) {
        int e = i + half;
        bool valid = (e < end);
        int s = g_csrc[valid ? e : i];
        float4 kk = *(const float4*)(g_k + (size_t)s * HDc + c);
        float4 vv = *(const float4*)(g_v + (size_t)s * HDc + c);
        float p = qv.x * kk.x + qv.y * kk.y + qv.z * kk.z + qv.w * kk.w;
        p += __shfl_xor_sync(0xffffffffu, p, 1);
        p += __shfl_xor_sync(0xffffffffu, p, 2);
        if (valid) {
            float nm = fmaxf(mm, p);
            float sc = __expf(mm - nm);
            float w = __expf(p - nm);
            ss = ss * sc + w;
            acc.x = acc.x * sc + w * vv.x;
            acc.y = acc.y * sc + w * vv.y;
            acc.z = acc.z * sc + w * vv.z;
            acc.w = acc.w * sc + w * vv.w;
            mm = nm;
        }
    }

    // merge the two halves' online-softmax states
    float om = __shfl_xor_sync(0xffffffffu, mm, 16);
    float os = __shfl_xor_sync(0xffffffffu, ss, 16);
    float4 oa;
    oa.x = __shfl_xor_sync(0xffffffffu, acc.x, 16);
    oa.y = __shfl_xor_sync(0xffffffffu, acc.y, 16);
    oa.z = __shfl_xor_sync(0xffffffffu, acc.z, 16);
    oa.w = __shfl_xor_sync(0xffffffffu, acc.w, 16);
    float M = fmaxf(mm, om);
    float e0 = (ss > 0.f) ? __expf(mm - M) : 0.f;
    float e1 = (os > 0.f) ? __expf(om - M) : 0.f;
    float S = ss * e0 + os * e1;
    float4 A;
    A.x = acc.x * e0 + oa.x * e1;
    A.y = acc.y * e0 + oa.y * e1;
    A.z = acc.z * e0 + oa.z * e1;
    A.w = acc.w * e0 + oa.w * e1;
    float inv = (S > 0.f) ? (1.0f / S) : 0.f;

    float4 sk = *(const float4*)(g_skip + (size_t)gw * HDc + c);
    float4 o;
    o.x = A.x * inv + sk.x;
    o.y = A.y * inv + sk.y;
    o.z = A.z * inv + sk.z;
    o.w = A.w * inv + sk.w;

    // LayerNorm: each channel appears in both halves -> divide by 128
    float sum = o.x + o.y + o.z + o.w;
    float sq  = o.x * o.x + o.y * o.y + o.z * o.z + o.w * o.w;
#pragma unroll
    for (int off = 16; off > 0; off >>= 1) {
        sum += __shfl_xor_sync(0xffffffffu, sum, off);
        sq  += __shfl_xor_sync(0xffffffffu, sq, off);
    }
    float mean = sum * (1.f / 128.f);
    float var  = sq * (1.f / 128.f) - mean * mean;
    float r = rsqrtf(var + 1e-5f);

    if (half == 0) {
        float4 g4 = *(const float4*)(ln_g + c);
        float4 b4 = *(const float4*)(ln_b + c);
        float4 oo;
        oo.x = (o.x - mean) * r * g4.x + b4.x;
        oo.y = (o.y - mean) * r * g4.y + b4.y;
        oo.z = (o.z - mean) * r * g4.z + b4.z;
        oo.w = (o.w - mean) * r * g4.w + b4.w;
        *(float4*)(out + (size_t)gw * HDc + c) = oo;
    }
}

// ---------------- launch ---------------------------------------------------
extern "C" void kernel_launch(void* const* d_in, const int* in_sizes, int n_in,
                              void* d_out, int out_size) {
    const float* feature = (const float*)d_in[0];
    const int*   src     = (const int*)d_in[1];
    const int*   dst     = (const int*)d_in[2];
    WPtrs wp;
    wp.W[0] = (const float*)d_in[3];
    wp.W[1] = (const float*)d_in[5];
    wp.W[2] = (const float*)d_in[7];
    wp.W[3] = (const float*)d_in[9];
    BiasPtrs bp;
    bp.b[0] = (const float*)d_in[4];
    bp.b[1] = (const float*)d_in[6];
    bp.b[2] = (const float*)d_in[8];
    bp.b[3] = (const float*)d_in[10];
    const float* ln_g = (const float*)d_in[11];
    const float* ln_b = (const float*)d_in[12];
    float* out = (float*)d_out;

    const int NB_SCAN = (NN + 1023) / 1024;  // 98

    cudaFuncSetAttribute(gemm_mma_k, cudaFuncAttributeMaxDynamicSharedMemorySize, SM_TOT);

    zero_k<<<(NN + 255) / 256, 256>>>();
    hist_k<<<(EE / 4 + 255) / 256, 256>>>(dst);
    wprep_k<<<(4 * 64 * 128 + 255) / 256, 256>>>(wp);
    scan_reduce_k<<<NB_SCAN, 1024>>>();
    scan_mid_k<<<1, 128>>>(NB_SCAN);

    gemm_mma_k<<<(NN + 255) / 256, 256, SM_TOT>>>(feature, bp);

    scan_final_k<<<NB_SCAN, 1024>>>();
    scatter_k<<<(EE / 4 + 255) / 256, 256>>>(src, dst);

    attn_k<<<(NN * 32 + 255) / 256, 256>>>(ln_g, ln_b, out);
}

// round 12
// speedup vs baseline: 1.2051x; 1.2051x over previous
#include <cuda_runtime.h>
#include <cuda_bf16.h>
#include <math_constants.h>
#include <cstdint>

// Problem constants (fixed shapes per reference)
constexpr int NN = 100000;   // nodes
constexpr int EE = 1600000;  // edges
constexpr int HDc = 64;      // H*D
constexpr int FIN = 128;

// ---------------- scratch (static device globals; no runtime alloc) -------
__device__ float g_q[(size_t)NN * HDc];
__device__ float g_k[(size_t)NN * HDc];
__device__ float g_v[(size_t)NN * HDc];
__device__ float g_skip[(size_t)NN * HDc];
__device__ int   g_cnt[NN];
__device__ int   g_rowstart[NN + 1];
__device__ int   g_cursor[NN];
__device__ int   g_csrc[EE];
__device__ int   g_bsum[128];
// Pre-split bf16 weights, TRANSPOSED: [4 matrices][64 n][128 k] (k contiguous)
__device__ __nv_bfloat16 g_Wh[4 * 64 * 128];
__device__ __nv_bfloat16 g_Wl[4 * 64 * 128];

// ---------------- CSR build ------------------------------------------------
__global__ void zero_k() {
    int i = blockIdx.x * blockDim.x + threadIdx.x;
    if (i < NN) g_cnt[i] = 0;
}

__global__ void hist_k(const int* __restrict__ dst) {
    int e = blockIdx.x * blockDim.x + threadIdx.x;
    if (e < EE) atomicAdd(&g_cnt[dst[e]], 1);
}

__global__ void scan_reduce_k() {
    __shared__ int sb[1024];
    int t = threadIdx.x;
    int i = blockIdx.x * 1024 + t;
    sb[t] = (i < NN) ? g_cnt[i] : 0;
    __syncthreads();
    for (int off = 512; off > 0; off >>= 1) {
        if (t < off) sb[t] += sb[t + off];
        __syncthreads();
    }
    if (t == 0) g_bsum[blockIdx.x] = sb[0];
}

__global__ void scan_mid_k(int nb) {
    __shared__ int sb[2][128];
    int t = threadIdx.x;
    int v = (t < nb) ? g_bsum[t] : 0;
    sb[0][t] = v;
    __syncthreads();
    int cur = 0;
    for (int off = 1; off < 128; off <<= 1) {
        int nv = sb[cur][t] + ((t >= off) ? sb[cur][t - off] : 0);
        sb[cur ^ 1][t] = nv;
        cur ^= 1;
        __syncthreads();
    }
    if (t < nb) g_bsum[t] = sb[cur][t] - v;  // exclusive
}

__global__ void scan_final_k() {
    __shared__ int sb[2][1024];
    int t = threadIdx.x;
    int i = blockIdx.x * 1024 + t;
    int v = (i < NN) ? g_cnt[i] : 0;
    sb[0][t] = v;
    __syncthreads();
    int cur = 0;
    for (int off = 1; off < 1024; off <<= 1) {
        int nv = sb[cur][t] + ((t >= off) ? sb[cur][t - off] : 0);
        sb[cur ^ 1][t] = nv;
        cur ^= 1;
        __syncthreads();
    }
    int incl = sb[cur][t];
    int base = g_bsum[blockIdx.x];
    if (i < NN) {
        int ex = base + incl - v;
        g_rowstart[i] = ex;
        g_cursor[i]   = ex;
        if (i == NN - 1) g_rowstart[NN] = ex + v;
    }
}

__global__ void scatter_k(const int* __restrict__ src, const int* __restrict__ dst) {
    int e = blockIdx.x * blockDim.x + threadIdx.x;
    if (e < EE) {
        int d = dst[e];
        int p = atomicAdd(&g_cursor[d], 1);
        g_csrc[p] = src[e];
    }
}

// ---------------- weight pre-split: fp32 [k][n] -> bf16 hi/lo W^T [n][k] ----
struct WPtrs { const float* W[4]; };

__global__ void wprep_k(WPtrs wp) {
    int e = blockIdx.x * blockDim.x + threadIdx.x;
    if (e >= 4 * 64 * 128) return;
    int m = e >> 13;
    int rest = e & 8191;
    int n = rest >> 7;     // 0..63
    int k = rest & 127;    // 0..127
    float x = wp.W[m][(size_t)k * 64 + n];
    __nv_bfloat16 hi = __float2bfloat16_rn(x);
    __nv_bfloat16 lo = __float2bfloat16_rn(x - __bfloat162float(hi));
    g_Wh[m * 8192 + n * 128 + k] = hi;
    g_Wl[m * 8192 + n * 128 + k] = lo;
}

// ---------------- mma.sync split-bf16 GEMM ---------------------------------
// D = A_hi*W_hi + A_hi*W_lo + A_lo*W_hi, fp32 accum (HMMA m16n8k16).
// Block: 256 thr = 8 warps. Warp (wm=wid>>2 in {0,1}, wn=wid&3 = matrix id).
// Warp tile: 32 rows x 64 cols of its matrix. Block: 2 M-tiles of 64 rows.
constexpr int PAD = 272;
constexpr int SW_H = 0;                       // 256 rows * 272 = 69632
constexpr int SW_L = 256 * PAD;               // 69632
constexpr int SA_H = 2 * SW_L;                // 139264 (64 rows * 272)
constexpr int SA_L = SA_H + 64 * PAD;         // 156672
constexpr int SM_TOT = SA_L + 64 * PAD;       // 174080

struct BiasPtrs { const float* b[4]; };

__device__ __forceinline__ void mma16816(float c[4], const uint32_t a[4],
                                         uint32_t b0, uint32_t b1) {
    asm volatile(
        "mma.sync.aligned.m16n8k16.row.col.f32.bf16.bf16.f32 "
        "{%0,%1,%2,%3}, {%4,%5,%6,%7}, {%8,%9}, {%0,%1,%2,%3};"
        : "+f"(c[0]), "+f"(c[1]), "+f"(c[2]), "+f"(c[3])
        : "r"(a[0]), "r"(a[1]), "r"(a[2]), "r"(a[3]), "r"(b0), "r"(b1));
}

__global__ void __launch_bounds__(256) gemm_mma_k(const float* __restrict__ feat,
                                                  BiasPtrs bp) {
    extern __shared__ char smem[];
    const int tid = threadIdx.x;
    const int wid = tid >> 5;
    const int lane = tid & 31;
    const int gid = lane >> 2;   // 0..7 (row within 8-block)
    const int tig = lane & 3;    // 0..3
    const int wm = wid >> 2;     // 0..1 : M half
    const int wn = wid & 3;      // 0..3 : matrix id

    // ---- stage all weights once (hi+lo, padded rows) ----
    {
        const uint4* wh = (const uint4*)g_Wh;
        const uint4* wl = (const uint4*)g_Wl;
        for (int i = tid; i < 4096; i += 256) {
            int mn = i >> 4;          // 0..255 (matrix*64 + n)
            int chunk = i & 15;       // 16-byte chunk within 256B row
            *(uint4*)(smem + SW_H + mn * PAD + chunk * 16) = wh[i];
            *(uint4*)(smem + SW_L + mn * PAD + chunk * 16) = wl[i];
        }
    }

    float* const outs[4] = {g_q, g_k, g_v, g_skip};
    const float* bias = bp.b[wn];
    const float scale = (wn == 0) ? 0.25f : 1.0f;
    float2 bvv[8];
#pragma unroll
    for (int ni = 0; ni < 8; ni++) bvv[ni] = *(const float2*)&bias[ni * 8 + tig * 2];

    for (int t = 0; t < 2; t++) {
        const int trow0 = blockIdx.x * 128 + t * 64;
        __syncthreads();   // W ready (t=0) / previous tile's frag reads done (t=1)

        // ---- stage A tile (64 rows x 128 k), split hi/lo ----
        for (int idx = tid; idx < 2048; idx += 256) {
            int r = idx >> 5;          // 0..63
            int k4 = idx & 31;         // float4 index (4 k each)
            int grow = trow0 + r;
            float4 a = (grow < NN)
                ? *(const float4*)&feat[(size_t)grow * FIN + k4 * 4]
                : make_float4(0.f, 0.f, 0.f, 0.f);
            __nv_bfloat16 h0 = __float2bfloat16_rn(a.x);
            __nv_bfloat16 h1 = __float2bfloat16_rn(a.y);
            __nv_bfloat16 h2 = __float2bfloat16_rn(a.z);
            __nv_bfloat16 h3 = __float2bfloat16_rn(a.w);
            __nv_bfloat16 l0 = __float2bfloat16_rn(a.x - __bfloat162float(h0));
            __nv_bfloat16 l1 = __float2bfloat16_rn(a.y - __bfloat162float(h1));
            __nv_bfloat16 l2 = __float2bfloat16_rn(a.z - __bfloat162float(h2));
            __nv_bfloat16 l3 = __float2bfloat16_rn(a.w - __bfloat162float(h3));
            uint2 hp, lp;
            hp.x = (uint32_t)__bfloat16_as_ushort(h0) | ((uint32_t)__bfloat16_as_ushort(h1) << 16);
            hp.y = (uint32_t)__bfloat16_as_ushort(h2) | ((uint32_t)__bfloat16_as_ushort(h3) << 16);
            lp.x = (uint32_t)__bfloat16_as_ushort(l0) | ((uint32_t)__bfloat16_as_ushort(l1) << 16);
            lp.y = (uint32_t)__bfloat16_as_ushort(l2) | ((uint32_t)__bfloat16_as_ushort(l3) << 16);
            *(uint2*)(smem + SA_H + r * PAD + k4 * 8) = hp;
            *(uint2*)(smem + SA_L + r * PAD + k4 * 8) = lp;
        }
        __syncthreads();

        // ---- main MMA loop ----
        float acc[2][8][4];
#pragma unroll
        for (int mi = 0; mi < 2; mi++)
#pragma unroll
            for (int ni = 0; ni < 8; ni++)
#pragma unroll
                for (int j = 0; j < 4; j++) acc[mi][ni][j] = 0.f;

#pragma unroll
        for (int ks = 0; ks < 8; ks++) {
            const int kcolB = (ks * 16 + tig * 2) * 2;  // byte offset of k pair
            uint32_t ah[2][4], al[2][4];
#pragma unroll
            for (int mi = 0; mi < 2; mi++) {
                const char* base = smem + (wm * 32 + mi * 16 + gid) * PAD + kcolB;
                ah[mi][0] = *(const uint32_t*)(base + SA_H);
                ah[mi][1] = *(const uint32_t*)(base + SA_H + 8 * PAD);
                ah[mi][2] = *(const uint32_t*)(base + SA_H + 16);
                ah[mi][3] = *(const uint32_t*)(base + SA_H + 8 * PAD + 16);
                al[mi][0] = *(const uint32_t*)(base + SA_L);
                al[mi][1] = *(const uint32_t*)(base + SA_L + 8 * PAD);
                al[mi][2] = *(const uint32_t*)(base + SA_L + 16);
                al[mi][3] = *(const uint32_t*)(base + SA_L + 8 * PAD + 16);
            }
            uint32_t bh[8][2], bl[8][2];
#pragma unroll
            for (int ni = 0; ni < 8; ni++) {
                const char* base = smem + (wn * 64 + ni * 8 + gid) * PAD + kcolB;
                bh[ni][0] = *(const uint32_t*)(base + SW_H);
                bh[ni][1] = *(const uint32_t*)(base + SW_H + 16);
                bl[ni][0] = *(const uint32_t*)(base + SW_L);
                bl[ni][1] = *(const uint32_t*)(base + SW_L + 16);
            }
#pragma unroll
            for (int mi = 0; mi < 2; mi++)
#pragma unroll
                for (int ni = 0; ni < 8; ni++) {
                    mma16816(acc[mi][ni], ah[mi], bh[ni][0], bh[ni][1]);
                    mma16816(acc[mi][ni], ah[mi], bl[ni][0], bl[ni][1]);
                    mma16816(acc[mi][ni], al[mi], bh[ni][0], bh[ni][1]);
                }
        }

        // ---- epilogue ----
        float* op = outs[wn];
#pragma unroll
        for (int mi = 0; mi < 2; mi++) {
            int r0 = trow0 + wm * 32 + mi * 16 + gid;
#pragma unroll
            for (int ni = 0; ni < 8; ni++) {
                int col = ni * 8 + tig * 2;
                float2 bv = bvv[ni];
                if (r0 < NN) {
                    float2 o;
                    o.x = (acc[mi][ni][0] + bv.x) * scale;
                    o.y = (acc[mi][ni][1] + bv.y) * scale;
                    *(float2*)&op[(size_t)r0 * HDc + col] = o;
                }
                if (r0 + 8 < NN) {
                    float2 o;
                    o.x = (acc[mi][ni][2] + bv.x) * scale;
                    o.y = (acc[mi][ni][3] + bv.y) * scale;
                    *(float2*)&op[(size_t)(r0 + 8) * HDc + col] = o;
                }
            }
        }
    }
}

// ---------------- fused attention + skip + LayerNorm -----------------------
// One warp per destination node. Lane l owns channels 2l,2l+1 (float2).
// Online softmax over incoming edges; zero float atomics. (R10 version.)
__global__ void __launch_bounds__(256) attn_k(const float* __restrict__ ln_g,
                                              const float* __restrict__ ln_b,
                                              float* __restrict__ out) {
    int gw = (blockIdx.x * blockDim.x + threadIdx.x) >> 5;
    int lane = threadIdx.x & 31;
    if (gw >= NN) return;
    const int n = gw;
    const int c = lane * 2;

    float2 qv = *(const float2*)(g_q + (size_t)n * HDc + c);
    int beg = g_rowstart[n];
    int end = g_rowstart[n + 1];

    float mm = -CUDART_INF_F, ss = 0.f, ax = 0.f, ay = 0.f;

    int i = beg;
    for (; i + 2 <= end; i += 2) {
        int s0 = g_csrc[i];
        int s1 = g_csrc[i + 1];
        float2 k0 = *(const float2*)(g_k + (size_t)s0 * HDc + c);
        float2 k1 = *(const float2*)(g_k + (size_t)s1 * HDc + c);
        float2 v0 = *(const float2*)(g_v + (size_t)s0 * HDc + c);
        float2 v1 = *(const float2*)(g_v + (size_t)s1 * HDc + c);
        float p0 = qv.x * k0.x + qv.y * k0.y;
        float p1 = qv.x * k1.x + qv.y * k1.y;
        p0 += __shfl_xor_sync(0xffffffffu, p0, 1);
        p1 += __shfl_xor_sync(0xffffffffu, p1, 1);
        p0 += __shfl_xor_sync(0xffffffffu, p0, 2);
        p1 += __shfl_xor_sync(0xffffffffu, p1, 2);
        p0 += __shfl_xor_sync(0xffffffffu, p0, 4);
        p1 += __shfl_xor_sync(0xffffffffu, p1, 4);
        float nm = fmaxf(mm, fmaxf(p0, p1));
        float sc = __expf(mm - nm);
        float w0 = __expf(p0 - nm);
        float w1 = __expf(p1 - nm);
        ss = ss * sc + w0 + w1;
        ax = ax * sc + w0 * v0.x + w1 * v1.x;
        ay = ay * sc + w0 * v0.y + w1 * v1.y;
        mm = nm;
    }
    if (i < end) {
        int s0 = g_csrc[i];
        float2 k0 = *(const float2*)(g_k + (size_t)s0 * HDc + c);
        float2 v0 = *(const float2*)(g_v + (size_t)s0 * HDc + c);
        float p0 = qv.x * k0.x + qv.y * k0.y;
        p0 += __shfl_xor_sync(0xffffffffu, p0, 1);
        p0 += __shfl_xor_sync(0xffffffffu, p0, 2);
        p0 += __shfl_xor_sync(0xffffffffu, p0, 4);
        float nm = fmaxf(mm, p0);
        float sc = __expf(mm - nm);
        float w0 = __expf(p0 - nm);
        ss = ss * sc + w0;
        ax = ax * sc + w0 * v0.x;
        ay = ay * sc + w0 * v0.y;
        mm = nm;
    }

    float inv = (ss > 0.f) ? (1.0f / ss) : 0.f;
    float2 sk = *(const float2*)(g_skip + (size_t)n * HDc + c);
    float ox = ax * inv + sk.x;
    float oy = ay * inv + sk.y;

    float sum = ox + oy;
    float sq  = ox * ox + oy * oy;
#pragma unroll
    for (int o = 16; o > 0; o >>= 1) {
        sum += __shfl_xor_sync(0xffffffffu, sum, o);
        sq  += __shfl_xor_sync(0xffffffffu, sq, o);
    }
    float mean = sum * (1.f / 64.f);
    float var  = sq * (1.f / 64.f) - mean * mean;
    float r = rsqrtf(var + 1e-5f);
    float2 g2 = *(const float2*)(ln_g + c);
    float2 b2 = *(const float2*)(ln_b + c);
    float2 o2;
    o2.x = (ox - mean) * r * g2.x + b2.x;
    o2.y = (oy - mean) * r * g2.y + b2.y;
    *(float2*)(out + (size_t)n * HDc + c) = o2;
}

// ---------------- launch ---------------------------------------------------
// Fork-join: the CSR chain (zero/hist/scan/scatter) runs on a side stream,
// overlapped with wprep+gemm on the main (captured) stream. Events express
// the dependency; cudaGraph capture turns this into parallel branches.
extern "C" void kernel_launch(void* const* d_in, const int* in_sizes, int n_in,
                              void* d_out, int out_size) {
    const float* feature = (const float*)d_in[0];
    const int*   src     = (const int*)d_in[1];
    const int*   dst     = (const int*)d_in[2];
    WPtrs wp;
    wp.W[0] = (const float*)d_in[3];
    wp.W[1] = (const float*)d_in[5];
    wp.W[2] = (const float*)d_in[7];
    wp.W[3] = (const float*)d_in[9];
    BiasPtrs bp;
    bp.b[0] = (const float*)d_in[4];
    bp.b[1] = (const float*)d_in[6];
    bp.b[2] = (const float*)d_in[8];
    bp.b[3] = (const float*)d_in[10];
    const float* ln_g = (const float*)d_in[11];
    const float* ln_b = (const float*)d_in[12];
    float* out = (float*)d_out;

    static cudaStream_t s2 = nullptr;
    static cudaEvent_t evFork = nullptr, evJoin = nullptr;
    if (s2 == nullptr) {
        cudaStreamCreateWithFlags(&s2, cudaStreamNonBlocking);
        cudaEventCreateWithFlags(&evFork, cudaEventDisableTiming);
        cudaEventCreateWithFlags(&evJoin, cudaEventDisableTiming);
    }

    const int NB_SCAN = (NN + 1023) / 1024;  // 98

    cudaFuncSetAttribute(gemm_mma_k, cudaFuncAttributeMaxDynamicSharedMemorySize, SM_TOT);

    // Fork: CSR chain on s2
    cudaEventRecord(evFork, 0);
    cudaStreamWaitEvent(s2, evFork, 0);
    zero_k<<<(NN + 255) / 256, 256, 0, s2>>>();
    hist_k<<<(EE + 255) / 256, 256, 0, s2>>>(dst);
    scan_reduce_k<<<NB_SCAN, 1024, 0, s2>>>();
    scan_mid_k<<<1, 128, 0, s2>>>(NB_SCAN);
    scan_final_k<<<NB_SCAN, 1024, 0, s2>>>();
    scatter_k<<<(EE + 255) / 256, 256, 0, s2>>>(src, dst);
    cudaEventRecord(evJoin, s2);

    // Main stream: projections (independent of CSR chain)
    wprep_k<<<(4 * 64 * 128 + 255) / 256, 256>>>(wp);
    gemm_mma_k<<<(NN + 127) / 128, 256, SM_TOT>>>(feature, bp);

    // Join, then attention consumes both
    cudaStreamWaitEvent(0, evJoin, 0);
    attn_k<<<(NN * 32 + 255) / 256, 256>>>(ln_g, ln_b, out);
}